// round 12
// baseline (speedup 1.0000x reference)
#include <cuda_runtime.h>

#define LSEQ 512
#define CIN  256
#define HID  32
#define PAIR 64

// Transposed scratch (producer pays transpose, consumer reads coalesced)
__device__ float g_sT[HID * LSEQ];            // g_sT[c][j]
__device__ float g_tmpT[LSEQ * HID * PAIR];   // g_tmpT[i][c][k]

// ---- packed f32x2 helpers (Blackwell FFMA2) ----
static __device__ __forceinline__ void upk2(unsigned long long v, float& a, float& b) {
    asm("mov.b64 {%0, %1}, %2;" : "=f"(a), "=f"(b) : "l"(v));
}
static __device__ __forceinline__ unsigned long long ffma2(
    unsigned long long a, unsigned long long b, unsigned long long c) {
    unsigned long long r;
    asm("fma.rn.f32x2 %0, %1, %2, %3;" : "=l"(r) : "l"(a), "l"(b), "l"(c));
    return r;
}
// direct 16B shared load into two u64 (no pack MOVs)
static __device__ __forceinline__ void lds_v2u64(
    unsigned long long& a, unsigned long long& b, unsigned int addr) {
    asm volatile("ld.shared.v2.u64 {%0, %1}, [%2];" : "=l"(a), "=l"(b) : "r"(addr));
}

// ============================================================
// K2 (identical to the R10-passing version):
// grid (2 kc-halves, 64 i-groups), 256 threads, dynamic smem.
// ============================================================
__global__ __launch_bounds__(256) void k2_fused(
    const float* __restrict__ seq, const float* __restrict__ W1,
    const float* __restrict__ b1, const float* __restrict__ W2)
{
    extern __shared__ float sm[];
    float* region0 = sm;            // 8448 floats
    float* region1 = sm + 8448;     // 8448 floats
    __shared__ float s8[8 * HID];   // 1 KB

    int tid = threadIdx.x;
    int bx  = blockIdx.x;           // kc half: k in [bx*32, bx*32+32)
    int i0  = blockIdx.y * 8;

    // ---- phase A: stage W1 transposed [d][h] stride 33 + seq rows ----
    {
        const float4* w1g = (const float4*)W1;
        #pragma unroll
        for (int p = 0; p < 8; p++) {
            int idx = tid + p * 256;      // 0..2047 float4s
            int h = idx >> 6, d4 = idx & 63;
            float4 v = w1g[idx];
            region0[(d4 * 4 + 0) * 33 + h] = v.x;
            region0[(d4 * 4 + 1) * 33 + h] = v.y;
            region0[(d4 * 4 + 2) * 33 + h] = v.z;
            region0[(d4 * 4 + 3) * 33 + h] = v.w;
        }
        const float4* sg = (const float4*)(seq + (size_t)i0 * CIN);
        float4* ss4 = (float4*)region1;
        #pragma unroll
        for (int p = 0; p < 2; p++) ss4[tid + p * 256] = sg[tid + p * 256];
    }
    __syncthreads();

    // ---- part 1: s8 (warp w -> i, lane -> h), 4 independent accumulators ----
    {
        int w = tid >> 5, h = tid & 31;
        float a0 = b1[h], a1 = 0.f, a2 = 0.f, a3 = 0.f;
        const float4* sv4 = (const float4*)(region1 + w * CIN);
        #pragma unroll 16
        for (int d4 = 0; d4 < 64; d4++) {
            float4 sv = sv4[d4];                       // uniform -> broadcast
            a0 += sv.x * region0[(d4 * 4 + 0) * 33 + h];
            a1 += sv.y * region0[(d4 * 4 + 1) * 33 + h];
            a2 += sv.z * region0[(d4 * 4 + 2) * 33 + h];
            a3 += sv.w * region0[(d4 * 4 + 3) * 33 + h];
        }
        float acc = (a0 + a1) + (a2 + a3);
        s8[tid] = acc;
        if (bx == 0) g_sT[(size_t)h * LSEQ + (i0 + w)] = acc;
    }
    __syncthreads();

    // ---- part 2: 4 pl-chunks of 256 kc rows each ----
    const float4* s84 = (const float4*)s8;
    #pragma unroll 1
    for (int pl = 0; pl < 4; pl++) {
        int p_abs = bx * 4 + pl;
        {
            const float4* w2g = (const float4*)(W2 + (size_t)p_abs * 256 * 32);
            #pragma unroll
            for (int q = 0; q < 8; q++) {
                int idx = tid + q * 256;          // 0..2047 float4s
                int r = idx >> 3, f4 = idx & 7;
                float4 v = w2g[idx];
                region0[r * 33 + f4 * 4 + 0] = v.x;
                region0[r * 33 + f4 * 4 + 1] = v.y;
                region0[r * 33 + f4 * 4 + 2] = v.z;
                region0[r * 33 + f4 * 4 + 3] = v.w;
            }
        }
        __syncthreads();

        {
            int kc_local = tid;
            int c = (p_abs * 256 + tid) & 31;
            int k_half = pl * 8 + (tid >> 5);
            float w_[32];
            #pragma unroll
            for (int e = 0; e < 32; e++) w_[e] = region0[kc_local * 33 + e];
            #pragma unroll
            for (int i = 0; i < 8; i++) {
                float c0 = 0.f, c1 = 0.f, c2 = 0.f, c3 = 0.f;
                #pragma unroll
                for (int q = 0; q < 8; q++) {
                    float4 sv = s84[i * 8 + q];   // uniform -> broadcast
                    c0 += sv.x * w_[q * 4 + 0];
                    c1 += sv.y * w_[q * 4 + 1];
                    c2 += sv.z * w_[q * 4 + 2];
                    c3 += sv.w * w_[q * 4 + 3];
                }
                region1[i * 1056 + k_half * 33 + c] = (c0 + c1) + (c2 + c3);
            }
        }
        __syncthreads();
    }

    // ---- final: buf -> g_tmpT[i][c][bx*32..+31], fully coalesced float4 STG ----
    #pragma unroll
    for (int q = 0; q < 8; q++) {
        int f = tid + q * 256;            // 0..2047 float4s
        int r = f >> 3, f4 = f & 7;
        int i = r >> 5, c = r & 31;
        float4 v;
        v.x = region1[i * 1056 + (f4 * 4 + 0) * 33 + c];
        v.y = region1[i * 1056 + (f4 * 4 + 1) * 33 + c];
        v.z = region1[i * 1056 + (f4 * 4 + 2) * 33 + c];
        v.w = region1[i * 1056 + (f4 * 4 + 3) * 33 + c];
        *(float4*)(g_tmpT + (size_t)(i0 + i) * 2048 + c * 64 + bx * 32 + f4 * 4) = v;
    }
}

// ============================================================
// K3: R7 shape (128 threads, 8j x 8k) + dup-s smem + direct u64 LDS.
// s_dup[c][2j] = {s,s} (32 KB): ld.shared.v2.u64 gives two (s,s) operands.
// tmp [c][k] (8 KB): ld.shared.v2.u64 gives (k0,k1),(k2,k3) pairs.
// -> zero pack MOVs in the inner loop: 32 FFMA2 + 6 LDS per c.
// ============================================================
__global__ __launch_bounds__(128, 4) void k3_main(
    const float* __restrict__ pair_rep, const float* __restrict__ b2,
    float* __restrict__ out)
{
    __shared__ float s_dup[32 * 256];   // [c][2j] duplicated, 32 KB
    __shared__ float tmp_sm[32 * 64];   // [c][k]  8 KB

    int tid = threadIdx.x;
    int i  = blockIdx.y;
    int jt = blockIdx.x;
    int tk = tid & 7;
    int tj = tid >> 3;

    const float* pbase = pair_rep + (((size_t)i * 512 + (size_t)jt * 128) * 64);

    // L2 prefetch of the 32 KB pair tile (256 lines, 2/thread)
    asm volatile("prefetch.global.L2 [%0];" :: "l"(pbase + (size_t)tid * 32));
    asm volatile("prefetch.global.L2 [%0];" :: "l"(pbase + (size_t)(tid + 128) * 32));

    // staging: coalesced LDG; s written duplicated via float2 {v,v} (contig STS.64)
    #pragma unroll
    for (int p = 0; p < 8; p++) {
        int idx = tid + p * 128;              // 0..1023 float4s
        int c = idx >> 5, j4 = idx & 31;      // j = j4*4 .. +3
        float4 v = ((const float4*)(g_sT + c * LSEQ + jt * 128))[j4];
        float2* d = (float2*)(s_dup + c * 256 + j4 * 8);
        d[0] = make_float2(v.x, v.x);
        d[1] = make_float2(v.y, v.y);
        d[2] = make_float2(v.z, v.z);
        d[3] = make_float2(v.w, v.w);
    }
    #pragma unroll
    for (int p = 0; p < 4; p++) {
        int idx = tid + p * 128;              // 0..511 float4s
        float4 v = ((const float4*)(g_tmpT + (size_t)i * 2048))[idx];
        ((float4*)tmp_sm)[idx] = v;
    }
    const float4* b24 = (const float4*)b2;
    float4 bz0 = b24[tk], bz1 = b24[8 + tk];
    __syncthreads();

    unsigned long long acc[8][4];
    #pragma unroll
    for (int a = 0; a < 8; a++)
        #pragma unroll
        for (int b = 0; b < 4; b++) acc[a][b] = 0ull;

    unsigned int tmp_base = (unsigned int)__cvta_generic_to_shared(tmp_sm) + tk * 16;
    unsigned int s_base   = (unsigned int)__cvta_generic_to_shared(s_dup) + tj * 64;

    #pragma unroll 4
    for (int c = 0; c < 32; c++) {
        unsigned long long tp0, tp1, tp2, tp3;
        lds_v2u64(tp0, tp1, tmp_base + c * 256);        // k = tk*4 .. +3
        lds_v2u64(tp2, tp3, tmp_base + c * 256 + 128);  // k = 32+tk*4 .. +3
        unsigned long long sd[8];
        lds_v2u64(sd[0], sd[1], s_base + c * 1024);
        lds_v2u64(sd[2], sd[3], s_base + c * 1024 + 16);
        lds_v2u64(sd[4], sd[5], s_base + c * 1024 + 32);
        lds_v2u64(sd[6], sd[7], s_base + c * 1024 + 48);
        #pragma unroll
        for (int jj = 0; jj < 8; jj++) {
            acc[jj][0] = ffma2(sd[jj], tp0, acc[jj][0]);
            acc[jj][1] = ffma2(sd[jj], tp1, acc[jj][1]);
            acc[jj][2] = ffma2(sd[jj], tp2, acc[jj][2]);
            acc[jj][3] = ffma2(sd[jj], tp3, acc[jj][3]);
        }
    }

    // epilogue: direct pair LDG (L2-warm) + add + streaming stores
    #pragma unroll
    for (int jj = 0; jj < 8; jj++) {
        int jloc = tj * 8 + jj;
        const float4* pp = (const float4*)(pbase + (size_t)jloc * 64);
        float4 p0 = __ldg(pp + tk);
        float4 p1 = __ldg(pp + 8 + tk);
        float x0, x1, x2, x3, x4, x5, x6, x7;
        upk2(acc[jj][0], x0, x1);
        upk2(acc[jj][1], x2, x3);
        upk2(acc[jj][2], x4, x5);
        upk2(acc[jj][3], x6, x7);
        float4 o0 = make_float4(x0 + p0.x + bz0.x, x1 + p0.y + bz0.y,
                                x2 + p0.z + bz0.z, x3 + p0.w + bz0.w);
        float4 o1 = make_float4(x4 + p1.x + bz1.x, x5 + p1.y + bz1.y,
                                x6 + p1.z + bz1.z, x7 + p1.w + bz1.w);
        size_t base = (((size_t)i * 512 + (size_t)(jt * 128 + jloc)) * 64);
        float4* op = (float4*)(out + base);
        __stcs(op + tk, o0);
        __stcs(op + 8 + tk, o1);
    }
}

// ============================================================
// Launch. Inputs (metadata order): seq, pair_rep, W1, b1, W2, b2.
// ============================================================
extern "C" void kernel_launch(void* const* d_in, const int* in_sizes, int n_in,
                              void* d_out, int out_size)
{
    const float* seq  = (const float*)d_in[0];
    const float* pair = (const float*)d_in[1];
    const float* W1   = (const float*)d_in[2];
    const float* b1   = (const float*)d_in[3];
    const float* W2   = (const float*)d_in[4];
    const float* b2   = (const float*)d_in[5];
    float* out = (float*)d_out;

    const int k2_smem = (8448 + 8448) * 4;   // 67.6 KB
    cudaFuncSetAttribute(k2_fused, cudaFuncAttributeMaxDynamicSharedMemorySize, k2_smem);

    dim3 g2(2, 64);
    k2_fused<<<g2, 256, k2_smem>>>(seq, W1, b1, W2);
    dim3 g3(4, LSEQ);
    k3_main<<<g3, 128>>>(pair, b2, out);
}